// round 4
// baseline (speedup 1.0000x reference)
#include <cuda_runtime.h>

typedef unsigned long long u64;

// ---- packed fp32x2 helpers (sm_100+; ptxas never emits these from C++) ----
static __device__ __forceinline__ u64 pack2(float x) {
    u64 r; asm("mov.b64 %0, {%1, %1};" : "=l"(r) : "f"(x)); return r;
}
static __device__ __forceinline__ u64 fma2(u64 a, u64 b, u64 c) {
    u64 d; asm("fma.rn.f32x2 %0, %1, %2, %3;" : "=l"(d) : "l"(a), "l"(b), "l"(c)); return d;
}
static __device__ __forceinline__ u64 add2(u64 a, u64 b) {
    u64 d; asm("add.rn.f32x2 %0, %1, %2;" : "=l"(d) : "l"(a), "l"(b)); return d;
}

#define B_  2
#define H_  96
#define W_  128
#define D_  32
#define C_  16
#define F_  16
#define TW  8
#define NSLAB 30
#define DSTR  17                    // [d][c] layout: c stride 1, d stride 16+1 pad
#define SSTR  545                   // slab stride: 32*17 + 1 (bank decorrelation)
#define IMG_FLOATS (NSLAB * SSTR)   // 16350
#define DVCOL  16352                // dv column start
#define DVLEN  16
#define WOFF   (DVCOL + DVLEN)      // 16368
#define WFLOATS (27 * 16 * 16)      // 6912
#define BPOFF  (WOFF + WFLOATS)     // 23280
#define SMEM_FLOATS (BPOFF + 32)    // 23312 floats = 93,248 B -> 2 CTAs/SM

extern __shared__ float smem[];

__global__ __launch_bounds__(128)
void sparse_conv3d_kernel(const float* __restrict__ images,
                          const int*   __restrict__ bp,
                          const float* __restrict__ kern,
                          const float* __restrict__ defv,
                          float*       __restrict__ out)
{
    float* s_img = smem;
    float* s_dv  = smem + DVCOL;
    float* s_w   = smem + WOFF;     // [tap][cc][ch][f] : tap*256 + cc*32 + ch*16 + f
    int*   s_bp  = (int*)(smem + BPOFF);

    const int tid = threadIdx.x;
    const int b   = blockIdx.z;
    const int h   = blockIdx.y;
    const int w0  = blockIdx.x * TW;
    const float dv = defv[0];

    // ---- stage weights, reindexed [tap][c][f] -> [tap][cc][ch][f], c = ch*8+cc ----
    for (int idx = tid; idx < WFLOATS / 4; idx += 128) {
        int g   = idx * 4;
        int tap = g >> 8;
        int c   = (g >> 4) & 15;
        int f4  = g & 15;
        float4 v = *(const float4*)(kern + g);
        int dst = (tap * 16 + (c & 7) * 2 + (c >> 3)) * 16 + f4;
        *(float4*)(s_w + dst) = v;
    }
    // ---- dv column (invalid depth taps read here) ----
    if (tid < DVLEN) s_dv[tid] = dv;
    // ---- base planes for 3x10 neighborhood ----
    if (tid < NSLAB) {
        int r  = tid / 10, q = tid - r * 10;
        int hc = min(max(h + r - 1, 0), H_ - 1);
        int wc = min(max(w0 + q - 1, 0), W_ - 1);
        s_bp[tid] = bp[(b * H_ + hc) * W_ + wc];
    }
    // ---- stage 30 slabs as [d][c]; spatially invalid slabs filled with dv ----
    {
        const int d  = tid >> 2;
        const int c4 = (tid & 3) * 4;
        int s = 0;
        #pragma unroll 1
        for (int r = 0; r < 3; ++r) {
            const int  hn = h + r - 1;
            const bool vh = (unsigned)hn < (unsigned)H_;
            #pragma unroll 1
            for (int q = 0; q < 10; ++q, ++s) {
                const int wn = w0 + q - 1;
                float4 v;
                if (vh && (unsigned)wn < (unsigned)W_) {
                    v = *(const float4*)&images[
                        ((((size_t)b * H_ + hn) * W_ + wn) * D_ + d) * C_ + c4];
                } else {
                    v = make_float4(dv, dv, dv, dv);
                }
                float* p = s_img + s * SSTR + d * DSTR + c4;
                p[0] = v.x; p[1] = v.y; p[2] = v.z; p[3] = v.w;
            }
        }
    }
    __syncthreads();

    // ---- compute layout: warp = dg (8 d's), lane = (wl, fpg, ch) ----
    const int lane = tid & 31;
    const int dg   = tid >> 5;        // 0..3 -> d in [8dg, 8dg+7]
    const int wl   = lane >> 2;       // 0..7
    const int fpg  = (lane >> 1) & 1; // f half: f in [8fpg, 8fpg+7]
    const int ch   = lane & 1;        // c half: c in [8ch, 8ch+7]
    const int dbase = dg * 8;
    const int w    = w0 + wl;
    const int bpc  = s_bp[11 + wl];

    u64 acc[8][4];
    #pragma unroll
    for (int t = 0; t < 8; ++t)
        #pragma unroll
        for (int p = 0; p < 4; ++p) acc[t][p] = 0ull;

    #pragma unroll 1
    for (int i = 0; i < 3; ++i) {
        #pragma unroll 1
        for (int j = 0; j < 3; ++j) {
            const int s = i * 10 + wl + j;
            const float* slab = s_img + s * SSTR + ch * 8;
            const int rel = bpc - s_bp[s];
            #pragma unroll 1
            for (int k = 0; k < 3; ++k) {
                const int off = rel + k - 1;
                // per-d pointers; invalid depth -> dv column
                const float* xp[8];
                #pragma unroll
                for (int t = 0; t < 8; ++t) {
                    int dd = dbase + t + off;
                    xp[t] = ((unsigned)dd < (unsigned)D_) ? (slab + dd * DSTR) : s_dv;
                }
                const float* wq = s_w + (((i * 3 + j) * 3 + k) * 16 + ch) * 16 + fpg * 8;
                #pragma unroll
                for (int cc = 0; cc < 8; ++cc) {
                    ulonglong2 wa = *(const ulonglong2*)(wq + cc * 32);
                    ulonglong2 wb = *(const ulonglong2*)(wq + cc * 32 + 4);
                    #pragma unroll
                    for (int t = 0; t < 8; ++t) {
                        u64 X = pack2(xp[t][cc]);
                        acc[t][0] = fma2(X, wa.x, acc[t][0]);
                        acc[t][1] = fma2(X, wa.y, acc[t][1]);
                        acc[t][2] = fma2(X, wb.x, acc[t][2]);
                        acc[t][3] = fma2(X, wb.y, acc[t][3]);
                    }
                }
            }
        }
    }

    // ---- reduce the c-half split (partner = lane^1) ----
    #pragma unroll
    for (int t = 0; t < 8; ++t)
        #pragma unroll
        for (int p = 0; p < 4; ++p) {
            u64 o = __shfl_xor_sync(0xffffffffu, acc[t][p], 1);
            acc[t][p] = add2(acc[t][p], o);
        }

    // ---- store: ch=0 writes t 0..3, ch=1 writes t 4..7 (both hold full sums) ----
    const size_t pixbase = ((((size_t)b * H_ + h) * W_ + w) * D_) * (size_t)F_;
    const int t0 = ch * 4;
    #pragma unroll
    for (int u = 0; u < 4; ++u) {
        int t = t0 + u;
        int d = dbase + t;
        float* o = out + pixbase + (size_t)d * F_ + fpg * 8;
        *(ulonglong2*)(o)     = make_ulonglong2(acc[t][0], acc[t][1]);
        *(ulonglong2*)(o + 4) = make_ulonglong2(acc[t][2], acc[t][3]);
    }
}

extern "C" void kernel_launch(void* const* d_in, const int* in_sizes, int n_in,
                              void* d_out, int out_size)
{
    // Identify inputs by element count (robust to metadata order):
    // images 12,582,912 | base_plane 24,576 | kernel 6,912 | default 1
    const float* images = nullptr;
    const int*   bp     = nullptr;
    const float* kern   = nullptr;
    const float* defv   = nullptr;
    for (int i = 0; i < n_in; ++i) {
        switch (in_sizes[i]) {
            case 12582912: images = (const float*)d_in[i]; break;
            case 24576:    bp     = (const int*)  d_in[i]; break;
            case 6912:     kern   = (const float*)d_in[i]; break;
            case 1:        defv   = (const float*)d_in[i]; break;
            default: break;
        }
    }
    if (!images) images = (const float*)d_in[0];
    if (!bp)     bp     = (const int*)  d_in[1];
    if (!kern)   kern   = (const float*)d_in[2];
    if (!defv)   defv   = (const float*)d_in[3];

    const int smem_bytes = SMEM_FLOATS * 4;
    (void)cudaFuncSetAttribute(sparse_conv3d_kernel,
                               cudaFuncAttributeMaxDynamicSharedMemorySize, smem_bytes);

    dim3 grid(W_ / TW, H_, B_);   // (16, 96, 2)
    sparse_conv3d_kernel<<<grid, 128, smem_bytes>>>(
        images, bp, kern, defv, (float*)d_out);
}

// round 5
// speedup vs baseline: 1.2356x; 1.2356x over previous
#include <cuda_runtime.h>

typedef unsigned long long u64;

// ---- packed fp32x2 helpers (sm_100+; ptxas never emits these from C++) ----
static __device__ __forceinline__ u64 pack2(float x) {
    u64 r; asm("mov.b64 %0, {%1, %1};" : "=l"(r) : "f"(x)); return r;
}
static __device__ __forceinline__ u64 fma2(u64 a, u64 b, u64 c) {
    u64 d; asm("fma.rn.f32x2 %0, %1, %2, %3;" : "=l"(d) : "l"(a), "l"(b), "l"(c)); return d;
}

#define B_  2
#define H_  96
#define W_  128
#define D_  32
#define C_  16
#define F_  16
#define TW  8
#define NSLAB 30
#define DSTR  17                    // [d][c]: c stride 1, d stride 16+1 pad
#define SSTR  561                   // 33 rows * 17 (row 32 = dv row); 561%32=17 (odd)
#define DVROW 544                   // 32*17
#define IMG_FLOATS (NSLAB * SSTR)   // 16830
#define WOFF   16832                // 16B-aligned weight base
#define WFLOATS (27 * 16 * 16)      // 6912
#define BPOFF  (WOFF + WFLOATS)     // 23744
#define SMEM_FLOATS (BPOFF + 32)    // 23776 floats = 95,104 B -> 2 CTAs/SM

extern __shared__ float smem[];

__global__ __launch_bounds__(64)
void sparse_conv3d_kernel(const float* __restrict__ images,
                          const int*   __restrict__ bp,
                          const float* __restrict__ kern,
                          const float* __restrict__ defv,
                          float*       __restrict__ out)
{
    float* s_img = smem;            // [slab][33 rows][17] ; row 32 = dv row
    float* s_w   = smem + WOFF;     // natural [tap][c][f]
    int*   s_bp  = (int*)(smem + BPOFF);

    const int tid = threadIdx.x;    // 64 threads
    const int b   = blockIdx.z;
    const int h   = blockIdx.y;
    const int w0  = blockIdx.x * TW;
    const float dv = defv[0];

    // ---- stage weights: straight copy, natural layout ----
    {
        const float4* src = (const float4*)kern;
        float4*       dst = (float4*)s_w;
        #pragma unroll
        for (int t = 0; t < WFLOATS / 4; t += 64) {
            int idx = t + tid;
            if (idx < WFLOATS / 4) dst[idx] = src[idx];
        }
    }
    // ---- dv rows: 30 slabs x 16 c ----
    for (int idx = tid; idx < NSLAB * 16; idx += 64) {
        int s = idx >> 4, c = idx & 15;
        s_img[s * SSTR + DVROW + c] = dv;
    }
    // ---- base planes for 3x10 neighborhood ----
    if (tid < NSLAB) {
        int r  = tid / 10, q = tid - r * 10;
        int hc = min(max(h + r - 1, 0), H_ - 1);
        int wc = min(max(w0 + q - 1, 0), W_ - 1);
        s_bp[tid] = bp[(b * H_ + hc) * W_ + wc];
    }
    // ---- stage 30 slabs as [d][c]; spatially invalid slabs = dv ----
    {
        const int d  = tid >> 1;          // 0..31
        const int c8 = (tid & 1) * 8;     // 0,8
        int s = 0;
        #pragma unroll 1
        for (int r = 0; r < 3; ++r) {
            const int  hn = h + r - 1;
            const bool vh = (unsigned)hn < (unsigned)H_;
            #pragma unroll 1
            for (int q = 0; q < 10; ++q, ++s) {
                const int wn = w0 + q - 1;
                float4 v0, v1;
                if (vh && (unsigned)wn < (unsigned)W_) {
                    const float* g = &images[
                        ((((size_t)b * H_ + hn) * W_ + wn) * D_ + d) * C_ + c8];
                    v0 = *(const float4*)g;
                    v1 = *(const float4*)(g + 4);
                } else {
                    v0 = make_float4(dv, dv, dv, dv);
                    v1 = v0;
                }
                float* p = s_img + s * SSTR + d * DSTR + c8;   // rows 17-stride: scalar stores
                p[0] = v0.x; p[1] = v0.y; p[2] = v0.z; p[3] = v0.w;
                p[4] = v1.x; p[5] = v1.y; p[6] = v1.z; p[7] = v1.w;
            }
        }
    }
    __syncthreads();

    // ---- compute: thread = (wl, dg: 8 d's, fpg: 8 f's) ----
    const int wl   = tid & 7;
    const int fpg  = (tid >> 3) & 1;
    const int dg   = tid >> 4;        // 0..3
    const int dbase = dg * 8;
    const int w    = w0 + wl;
    const int bpc  = s_bp[11 + wl];

    u64 acc[8][4];
    #pragma unroll
    for (int t = 0; t < 8; ++t)
        #pragma unroll
        for (int p = 0; p < 4; ++p) acc[t][p] = 0ull;

    #pragma unroll 1
    for (int i = 0; i < 3; ++i) {
        #pragma unroll 1
        for (int j = 0; j < 3; ++j) {
            const int s   = i * 10 + wl + j;
            const int rel = bpc - s_bp[s];
            // 10-row depth window: u -> dd = dbase + rel - 1 + u ; invalid -> dv row
            int xoff[10];
            #pragma unroll
            for (int u = 0; u < 10; ++u) {
                int dd  = dbase + rel - 1 + u;
                int row = ((unsigned)dd < (unsigned)D_) ? dd : 32;
                xoff[u] = s * SSTR + row * DSTR;
            }
            const float* wp = s_w + ((i * 3 + j) * 3 * 16) * 16 + fpg * 8;
            #pragma unroll 1
            for (int cc = 0; cc < 16; ++cc) {
                u64 X[10];
                #pragma unroll
                for (int u = 0; u < 10; ++u)
                    X[u] = pack2(s_img[xoff[u] + cc]);
                const float* wc = wp + cc * 16;
                #pragma unroll
                for (int k = 0; k < 3; ++k) {
                    ulonglong2 wa = *(const ulonglong2*)(wc + k * 256);
                    ulonglong2 wb = *(const ulonglong2*)(wc + k * 256 + 4);
                    #pragma unroll
                    for (int t = 0; t < 8; ++t) {
                        const u64 Xv = X[t + k];
                        acc[t][0] = fma2(Xv, wa.x, acc[t][0]);
                        acc[t][1] = fma2(Xv, wa.y, acc[t][1]);
                        acc[t][2] = fma2(Xv, wb.x, acc[t][2]);
                        acc[t][3] = fma2(Xv, wb.y, acc[t][3]);
                    }
                }
            }
        }
    }

    // ---- store: thread owns 8 d's x 8 f's (32B per d, 16B-aligned) ----
    const size_t pixbase = ((((size_t)b * H_ + h) * W_ + w) * D_) * (size_t)F_;
    #pragma unroll
    for (int t = 0; t < 8; ++t) {
        float* o = out + pixbase + (size_t)(dbase + t) * F_ + fpg * 8;
        *(ulonglong2*)(o)     = make_ulonglong2(acc[t][0], acc[t][1]);
        *(ulonglong2*)(o + 4) = make_ulonglong2(acc[t][2], acc[t][3]);
    }
}

extern "C" void kernel_launch(void* const* d_in, const int* in_sizes, int n_in,
                              void* d_out, int out_size)
{
    // Identify inputs by element count (robust to metadata order):
    // images 12,582,912 | base_plane 24,576 | kernel 6,912 | default 1
    const float* images = nullptr;
    const int*   bp     = nullptr;
    const float* kern   = nullptr;
    const float* defv   = nullptr;
    for (int i = 0; i < n_in; ++i) {
        switch (in_sizes[i]) {
            case 12582912: images = (const float*)d_in[i]; break;
            case 24576:    bp     = (const int*)  d_in[i]; break;
            case 6912:     kern   = (const float*)d_in[i]; break;
            case 1:        defv   = (const float*)d_in[i]; break;
            default: break;
        }
    }
    if (!images) images = (const float*)d_in[0];
    if (!bp)     bp     = (const int*)  d_in[1];
    if (!kern)   kern   = (const float*)d_in[2];
    if (!defv)   defv   = (const float*)d_in[3];

    const int smem_bytes = SMEM_FLOATS * 4;
    (void)cudaFuncSetAttribute(sparse_conv3d_kernel,
                               cudaFuncAttributeMaxDynamicSharedMemorySize, smem_bytes);

    dim3 grid(W_ / TW, H_, B_);   // (16, 96, 2)
    sparse_conv3d_kernel<<<grid, 64, smem_bytes>>>(
        images, bp, kern, defv, (float*)d_out);
}

// round 6
// speedup vs baseline: 1.6738x; 1.3546x over previous
#include <cuda_runtime.h>

typedef unsigned long long u64;

// ---- packed fp32x2 helpers (sm_100+; ptxas never emits these from C++) ----
static __device__ __forceinline__ u64 pack2(float x) {
    u64 r; asm("mov.b64 %0, {%1, %1};" : "=l"(r) : "f"(x)); return r;
}
static __device__ __forceinline__ u64 fma2(u64 a, u64 b, u64 c) {
    u64 d; asm("fma.rn.f32x2 %0, %1, %2, %3;" : "=l"(d) : "l"(a), "l"(b), "l"(c)); return d;
}
static __device__ __forceinline__ u64 add2(u64 a, u64 b) {
    u64 d; asm("add.rn.f32x2 %0, %1, %2;" : "=l"(d) : "l"(a), "l"(b)); return d;
}

#define B_  2
#define H_  96
#define W_  128
#define D_  32
#define C_  16
#define F_  16
#define TW  8
#define NSLAB 30
#define DSTR  17                    // [d][c]: c stride 1, d stride 16+1 pad
#define SSTR  561                   // 33 rows * 17 (row 32 = dv row)
#define DVROW 544                   // 32*17
#define IMG_FLOATS (NSLAB * SSTR)   // 16830
#define WOFF   16832                // 16B-aligned weight base
#define WFLOATS (27 * 16 * 16)      // 6912
#define BPOFF  (WOFF + WFLOATS)     // 23744
#define SMEM_FLOATS (BPOFF + 32)    // 23776 floats = 95,104 B -> 2 CTAs/SM

extern __shared__ float smem[];

__global__ __launch_bounds__(128)
void sparse_conv3d_kernel(const float* __restrict__ images,
                          const int*   __restrict__ bp,
                          const float* __restrict__ kern,
                          const float* __restrict__ defv,
                          float*       __restrict__ out)
{
    float* s_img = smem;            // [slab][33 rows][17] ; row 32 = dv row
    float* s_w   = smem + WOFF;     // natural [tap][c][f]
    int*   s_bp  = (int*)(smem + BPOFF);

    const int tid = threadIdx.x;    // 128 threads
    const int b   = blockIdx.z;
    const int h   = blockIdx.y;
    const int w0  = blockIdx.x * TW;
    const float dv = defv[0];

    // ---- stage weights: straight copy, natural layout ----
    {
        const float4* src = (const float4*)kern;
        float4*       dst = (float4*)s_w;
        #pragma unroll
        for (int t = 0; t < WFLOATS / 4; t += 128) {
            int idx = t + tid;
            if (idx < WFLOATS / 4) dst[idx] = src[idx];
        }
    }
    // ---- dv rows: 30 slabs x 16 c ----
    for (int idx = tid; idx < NSLAB * 16; idx += 128) {
        int s = idx >> 4, c = idx & 15;
        s_img[s * SSTR + DVROW + c] = dv;
    }
    // ---- base planes for 3x10 neighborhood ----
    if (tid < NSLAB) {
        int r  = tid / 10, q = tid - r * 10;
        int hc = min(max(h + r - 1, 0), H_ - 1);
        int wc = min(max(w0 + q - 1, 0), W_ - 1);
        s_bp[tid] = bp[(b * H_ + hc) * W_ + wc];
    }
    // ---- stage 30 slabs as [d][c]; spatially invalid slabs = dv ----
    {
        const int d  = tid >> 2;          // 0..31
        const int c4 = (tid & 3) * 4;     // 0,4,8,12
        int s = 0;
        #pragma unroll 1
        for (int r = 0; r < 3; ++r) {
            const int  hn = h + r - 1;
            const bool vh = (unsigned)hn < (unsigned)H_;
            #pragma unroll 1
            for (int q = 0; q < 10; ++q, ++s) {
                const int wn = w0 + q - 1;
                float4 v;
                if (vh && (unsigned)wn < (unsigned)W_) {
                    v = *(const float4*)&images[
                        ((((size_t)b * H_ + hn) * W_ + wn) * D_ + d) * C_ + c4];
                } else {
                    v = make_float4(dv, dv, dv, dv);
                }
                float* p = s_img + s * SSTR + d * DSTR + c4;
                p[0] = v.x; p[1] = v.y; p[2] = v.z; p[3] = v.w;
            }
        }
    }
    __syncthreads();

    // ---- compute: warp pair splits C. thread = (wl, fpg, dg) x cgrp ----
    const int tp    = tid & 63;
    const int cgrp  = tid >> 6;       // 0: c 0-7, 1: c 8-15
    const int wl    = tp & 7;
    const int fpg   = (tp >> 3) & 1;
    const int dg    = tp >> 4;        // 0..3
    const int dbase = dg * 8;
    const int w     = w0 + wl;
    const int bpc   = s_bp[11 + wl];
    const int cbase = cgrp * 8;

    u64 acc[8][4];
    #pragma unroll
    for (int t = 0; t < 8; ++t)
        #pragma unroll
        for (int p = 0; p < 4; ++p) acc[t][p] = 0ull;

    #pragma unroll 1
    for (int i = 0; i < 3; ++i) {
        #pragma unroll 1
        for (int j = 0; j < 3; ++j) {
            const int s   = i * 10 + wl + j;
            const int rel = bpc - s_bp[s];
            // 10-row depth window: u -> dd = dbase + rel - 1 + u ; invalid -> dv row
            int xoff[10];
            #pragma unroll
            for (int u = 0; u < 10; ++u) {
                int dd  = dbase + rel - 1 + u;
                int row = ((unsigned)dd < (unsigned)D_) ? dd : 32;
                xoff[u] = s * SSTR + row * DSTR + cbase;
            }
            const float* wp = s_w + (i * 3 + j) * 768 + cbase * 16 + fpg * 8;
            #pragma unroll 1
            for (int cc = 0; cc < 8; ++cc) {
                u64 X[10];
                #pragma unroll
                for (int u = 0; u < 10; ++u)
                    X[u] = pack2(s_img[xoff[u] + cc]);
                const float* wc = wp + cc * 16;
                #pragma unroll
                for (int k = 0; k < 3; ++k) {
                    ulonglong2 wa = *(const ulonglong2*)(wc + k * 256);
                    ulonglong2 wb = *(const ulonglong2*)(wc + k * 256 + 4);
                    #pragma unroll
                    for (int t = 0; t < 8; ++t) {
                        const u64 Xv = X[t + k];
                        acc[t][0] = fma2(Xv, wa.x, acc[t][0]);
                        acc[t][1] = fma2(Xv, wa.y, acc[t][1]);
                        acc[t][2] = fma2(Xv, wb.x, acc[t][2]);
                        acc[t][3] = fma2(Xv, wb.y, acc[t][3]);
                    }
                }
            }
        }
    }

    // ---- reduce the c-split: group 1 stages partials, group 0 adds+stores ----
    __syncthreads();                       // slabs dead; reuse as staging
    u64* s_red = (u64*)smem;               // 64 threads x 34 u64 stride (16B aligned)
    if (cgrp == 1) {
        u64* dst = s_red + tp * 34;
        #pragma unroll
        for (int t = 0; t < 8; ++t) {
            *(ulonglong2*)(dst + t * 4)     = make_ulonglong2(acc[t][0], acc[t][1]);
            *(ulonglong2*)(dst + t * 4 + 2) = make_ulonglong2(acc[t][2], acc[t][3]);
        }
    }
    __syncthreads();
    if (cgrp == 0) {
        const u64* src = s_red + tp * 34;
        const size_t pixbase = ((((size_t)b * H_ + h) * W_ + w) * D_) * (size_t)F_;
        #pragma unroll
        for (int t = 0; t < 8; ++t) {
            ulonglong2 pa = *(const ulonglong2*)(src + t * 4);
            ulonglong2 pb = *(const ulonglong2*)(src + t * 4 + 2);
            float* o = out + pixbase + (size_t)(dbase + t) * F_ + fpg * 8;
            *(ulonglong2*)(o)     = make_ulonglong2(add2(acc[t][0], pa.x),
                                                    add2(acc[t][1], pa.y));
            *(ulonglong2*)(o + 4) = make_ulonglong2(add2(acc[t][2], pb.x),
                                                    add2(acc[t][3], pb.y));
        }
    }
}

extern "C" void kernel_launch(void* const* d_in, const int* in_sizes, int n_in,
                              void* d_out, int out_size)
{
    // Identify inputs by element count (robust to metadata order):
    // images 12,582,912 | base_plane 24,576 | kernel 6,912 | default 1
    const float* images = nullptr;
    const int*   bp     = nullptr;
    const float* kern   = nullptr;
    const float* defv   = nullptr;
    for (int i = 0; i < n_in; ++i) {
        switch (in_sizes[i]) {
            case 12582912: images = (const float*)d_in[i]; break;
            case 24576:    bp     = (const int*)  d_in[i]; break;
            case 6912:     kern   = (const float*)d_in[i]; break;
            case 1:        defv   = (const float*)d_in[i]; break;
            default: break;
        }
    }
    if (!images) images = (const float*)d_in[0];
    if (!bp)     bp     = (const int*)  d_in[1];
    if (!kern)   kern   = (const float*)d_in[2];
    if (!defv)   defv   = (const float*)d_in[3];

    const int smem_bytes = SMEM_FLOATS * 4;
    (void)cudaFuncSetAttribute(sparse_conv3d_kernel,
                               cudaFuncAttributeMaxDynamicSharedMemorySize, smem_bytes);

    dim3 grid(W_ / TW, H_, B_);   // (16, 96, 2)
    sparse_conv3d_kernel<<<grid, 128, smem_bytes>>>(
        images, bp, kern, defv, (float*)d_out);
}

// round 8
// speedup vs baseline: 1.7177x; 1.0263x over previous
#include <cuda_runtime.h>

typedef unsigned long long u64;

// ---- packed fp32x2 helpers (sm_100+; ptxas never emits these from C++) ----
static __device__ __forceinline__ u64 pack2(float x) {
    u64 r; asm("mov.b64 %0, {%1, %1};" : "=l"(r) : "f"(x)); return r;
}
static __device__ __forceinline__ u64 fma2(u64 a, u64 b, u64 c) {
    u64 d; asm("fma.rn.f32x2 %0, %1, %2, %3;" : "=l"(d) : "l"(a), "l"(b), "l"(c)); return d;
}
static __device__ __forceinline__ u64 add2(u64 a, u64 b) {
    u64 d; asm("add.rn.f32x2 %0, %1, %2;" : "=l"(d) : "l"(a), "l"(b)); return d;
}

#define B_  2
#define H_  96
#define W_  128
#define D_  32
#define C_  16
#define F_  16
#define TW  8
#define NSLAB 30
#define DSTR  17                    // [d][c]: c stride 1, d stride 16+1 pad
#define SSTR  561                   // 33 rows * 17 (row 32 = dv row)
#define DVROW 544                   // 32*17
#define IMG_FLOATS (NSLAB * SSTR)   // 16830
#define WOFF   16832                // 16B-aligned weight base
#define WFLOATS (27 * 16 * 16)      // 6912
#define BPOFF  (WOFF + WFLOATS)     // 23744
#define SMEM_FLOATS (BPOFF + 32)    // 23776 floats = 95,104 B -> 2 CTAs/SM

extern __shared__ float smem[];

__global__ __launch_bounds__(256)
void sparse_conv3d_kernel(const float* __restrict__ images,
                          const int*   __restrict__ bp,
                          const float* __restrict__ kern,
                          const float* __restrict__ defv,
                          float*       __restrict__ out)
{
    float* s_img = smem;            // [slab][33 rows][17] ; row 32 = dv row
    float* s_w   = smem + WOFF;     // natural [tap][c][f]
    int*   s_bp  = (int*)(smem + BPOFF);

    const int tid = threadIdx.x;    // 256 threads
    const int b   = blockIdx.z;
    const int h   = blockIdx.y;
    const int w0  = blockIdx.x * TW;
    const float dv = defv[0];

    // ---- stage weights: straight copy, natural layout ----
    {
        const float4* src = (const float4*)kern;
        float4*       dst = (float4*)s_w;
        #pragma unroll
        for (int t = 0; t < WFLOATS / 4; t += 256) {
            int idx = t + tid;
            if (idx < WFLOATS / 4) dst[idx] = src[idx];
        }
    }
    // ---- dv rows: 30 slabs x 16 c ----
    for (int idx = tid; idx < NSLAB * 16; idx += 256) {
        int s = idx >> 4, c = idx & 15;
        s_img[s * SSTR + DVROW + c] = dv;
    }
    // ---- base planes for 3x10 neighborhood ----
    if (tid < NSLAB) {
        int r  = tid / 10, q = tid - r * 10;
        int hc = min(max(h + r - 1, 0), H_ - 1);
        int wc = min(max(w0 + q - 1, 0), W_ - 1);
        s_bp[tid] = bp[(b * H_ + hc) * W_ + wc];
    }
    // ---- stage 30 slabs as [d][c]; spatially invalid slabs = dv ----
    {
        const int d  = tid >> 3;          // 0..31
        const int c2 = (tid & 7) * 2;     // 0,2,..,14
        int s = 0;
        #pragma unroll 1
        for (int r = 0; r < 3; ++r) {
            const int  hn = h + r - 1;
            const bool vh = (unsigned)hn < (unsigned)H_;
            #pragma unroll 1
            for (int q = 0; q < 10; ++q, ++s) {
                const int wn = w0 + q - 1;
                float2 v;
                if (vh && (unsigned)wn < (unsigned)W_) {
                    v = *(const float2*)&images[
                        ((((size_t)b * H_ + hn) * W_ + wn) * D_ + d) * C_ + c2];
                } else {
                    v = make_float2(dv, dv);
                }
                float* p = s_img + s * SSTR + d * DSTR + c2;
                p[0] = v.x; p[1] = v.y;
            }
        }
    }
    __syncthreads();

    // ---- compute: 2 c-groups x (wl 8, fq 4, dg 4). thread = 8 d x 2 f-pairs ----
    const int tp    = tid & 127;
    const int cgrp  = tid >> 7;       // 0: c 0-7, 1: c 8-15
    const int wl    = tp & 7;
    const int fq    = (tp >> 3) & 3;  // f quarter: f in [4fq, 4fq+3]
    const int dg    = tp >> 5;        // 0..3
    const int dbase = dg * 8;
    const int w     = w0 + wl;
    const int bpc   = s_bp[11 + wl];
    const int cbase = cgrp * 8;

    u64 acc[8][2];
    #pragma unroll
    for (int t = 0; t < 8; ++t) { acc[t][0] = 0ull; acc[t][1] = 0ull; }

    #pragma unroll 1
    for (int i = 0; i < 3; ++i) {
        #pragma unroll 1
        for (int j = 0; j < 3; ++j) {
            const int s   = i * 10 + wl + j;
            const int rel = bpc - s_bp[s];
            // 10-row depth window: u -> dd = dbase + rel - 1 + u ; invalid -> dv row
            int xoff[10];
            #pragma unroll
            for (int u = 0; u < 10; ++u) {
                int dd  = dbase + rel - 1 + u;
                int row = ((unsigned)dd < (unsigned)D_) ? dd : 32;
                xoff[u] = s * SSTR + row * DSTR + cbase;
            }
            const float* wp = s_w + (i * 3 + j) * 768 + cbase * 16 + fq * 4;
            #pragma unroll 1
            for (int cc = 0; cc < 8; ++cc) {
                u64 X[10];
                #pragma unroll
                for (int u = 0; u < 10; ++u)
                    X[u] = pack2(s_img[xoff[u] + cc]);
                const float* wc = wp + cc * 16;
                #pragma unroll
                for (int k = 0; k < 3; ++k) {
                    ulonglong2 wa = *(const ulonglong2*)(wc + k * 256);
                    #pragma unroll
                    for (int t = 0; t < 8; ++t) {
                        const u64 Xv = X[t + k];
                        acc[t][0] = fma2(Xv, wa.x, acc[t][0]);
                        acc[t][1] = fma2(Xv, wa.y, acc[t][1]);
                    }
                }
            }
        }
    }

    // ---- reduce the c-split: group 1 stages partials, group 0 adds+stores ----
    __syncthreads();                       // slabs dead; reuse as staging
    u64* s_red = (u64*)smem;               // 128 threads x 18 u64 stride (16B aligned)
    if (cgrp == 1) {
        u64* dst = s_red + tp * 18;
        #pragma unroll
        for (int t = 0; t < 8; ++t)
            *(ulonglong2*)(dst + t * 2) = make_ulonglong2(acc[t][0], acc[t][1]);
    }
    __syncthreads();
    if (cgrp == 0) {
        const u64* src = s_red + tp * 18;
        const size_t pixbase = ((((size_t)b * H_ + h) * W_ + w) * D_) * (size_t)F_;
        #pragma unroll
        for (int t = 0; t < 8; ++t) {
            ulonglong2 pa = *(const ulonglong2*)(src + t * 2);
            float* o = out + pixbase + (size_t)(dbase + t) * F_ + fq * 4;
            *(ulonglong2*)o = make_ulonglong2(add2(acc[t][0], pa.x),
                                              add2(acc[t][1], pa.y));
        }
    }
}

extern "C" void kernel_launch(void* const* d_in, const int* in_sizes, int n_in,
                              void* d_out, int out_size)
{
    // Identify inputs by element count (robust to metadata order):
    // images 12,582,912 | base_plane 24,576 | kernel 6,912 | default 1
    const float* images = nullptr;
    const int*   bp     = nullptr;
    const float* kern   = nullptr;
    const float* defv   = nullptr;
    for (int i = 0; i < n_in; ++i) {
        switch (in_sizes[i]) {
            case 12582912: images = (const float*)d_in[i]; break;
            case 24576:    bp     = (const int*)  d_in[i]; break;
            case 6912:     kern   = (const float*)d_in[i]; break;
            case 1:        defv   = (const float*)d_in[i]; break;
            default: break;
        }
    }
    if (!images) images = (const float*)d_in[0];
    if (!bp)     bp     = (const int*)  d_in[1];
    if (!kern)   kern   = (const float*)d_in[2];
    if (!defv)   defv   = (const float*)d_in[3];

    const int smem_bytes = SMEM_FLOATS * 4;
    (void)cudaFuncSetAttribute(sparse_conv3d_kernel,
                               cudaFuncAttributeMaxDynamicSharedMemorySize, smem_bytes);

    dim3 grid(W_ / TW, H_, B_);   // (16, 96, 2)
    sparse_conv3d_kernel<<<grid, 256, smem_bytes>>>(
        images, bp, kern, defv, (float*)d_out);
}